// round 10
// baseline (speedup 1.0000x reference)
#include <cuda_runtime.h>
#include <cuda_bf16.h>

// out[bt, i*16 + j] = x[bt, i] * W[i, j] + b[i, j]
// 256 MB fp32 write stream + 16 MB x read.
// R9: clean DRAM read/write-turnaround test. Kernel A prefetches ALL of x
// into L2 (evict_last; L2 persists across launches). Kernel B is the best
// dense store loop (R3): its x loads hit L2, so DRAM sees a pure write
// stream with no read/write bus turnaround.

#define C_IN   128
#define C_OUT  16
#define TOTAL_F8 8388608u               // 2^23 float8 units
#define X_LINES  131072u                // 16 MB / 128B lines

#define NBLOCKS  (148 * 8)
#define NTHREADS 256
#define STRIDE   ((unsigned)NBLOCKS * NTHREADS)   // 303,104 (multiple of 256)

// ---- Kernel A: pin x in L2 (evict_last), one 128B line per thread ----
__global__ __launch_bounds__(256)
void x_prefetch_kernel(const float* __restrict__ x)
{
    const unsigned t = blockIdx.x * 256u + threadIdx.x;   // 0 .. 131071
    const float* p = x + (size_t)t * 32;                  // 32 floats = 128B
    asm volatile("prefetch.global.L2::evict_last [%0];" :: "l"(p));
}

// ---- Kernel B: dense write stream (R3 structure, best kernel time) ----
__global__ __launch_bounds__(NTHREADS, 8)
void real_embedding_kernel(const float* __restrict__ x,
                           const float* __restrict__ W,
                           const float* __restrict__ b,
                           float* __restrict__ out)
{
    const unsigned tid0 = blockIdx.x * NTHREADS + threadIdx.x;

    // STRIDE multiple of 256 -> per-thread (i, h) loop-invariant.
    const unsigned h = tid0 & 1u;
    const unsigned i = (tid0 >> 1) & 127u;

    const float4* W4 = (const float4*)(W + i * C_OUT + h * 8);
    const float4* B4 = (const float4*)(b + i * C_OUT + h * 8);
    const float4 w0 = W4[0], w1 = W4[1];
    const float4 c0 = B4[0], c1 = B4[1];

    const unsigned bt_step = STRIDE >> 8;
    unsigned bt = tid0 >> 8;

#pragma unroll 1
    for (unsigned gid = tid0; gid < TOTAL_F8; gid += STRIDE, bt += bt_step) {
        const float xv = __ldg(x + (size_t)bt * C_IN + i);   // L2 hit (pinned)

        const float r0 = fmaf(xv, w0.x, c0.x), r1 = fmaf(xv, w0.y, c0.y);
        const float r2 = fmaf(xv, w0.z, c0.z), r3 = fmaf(xv, w0.w, c0.w);
        const float r4 = fmaf(xv, w1.x, c1.x), r5 = fmaf(xv, w1.y, c1.y);
        const float r6 = fmaf(xv, w1.z, c1.z), r7 = fmaf(xv, w1.w, c1.w);

        float* dst = out + (size_t)gid * 8;   // warp-dense 1KB stores
        asm volatile("st.global.cs.v8.f32 [%0], {%1,%2,%3,%4,%5,%6,%7,%8};" ::
            "l"(dst), "f"(r0),"f"(r1),"f"(r2),"f"(r3),
                      "f"(r4),"f"(r5),"f"(r6),"f"(r7) : "memory");
    }
}

extern "C" void kernel_launch(void* const* d_in, const int* in_sizes, int n_in,
                              void* d_out, int out_size) {
    const float* x = (const float*)d_in[0];
    const float* W = (const float*)d_in[1];
    const float* b = (const float*)d_in[2];
    float* out = (float*)d_out;

    (void)in_sizes; (void)n_in; (void)out_size;

    // A: 512 blocks * 256 threads = exactly 131072 prefetches (16 MB of x).
    x_prefetch_kernel<<<512, 256>>>(x);
    // B: pure write stream; x loads hit L2.
    real_embedding_kernel<<<NBLOCKS, NTHREADS>>>(x, W, b, out);
}

// round 11
// speedup vs baseline: 1.0064x; 1.0064x over previous
#include <cuda_runtime.h>
#include <cuda_bf16.h>

// out[bt, i*16 + j] = x[bt, i] * W[i, j] + b[i, j]
// B*T = 32768, C_IN = 128, C_OUT = 16 -> 256 MB fp32 output write stream.
//
// Final kernel after 9 rounds of roofline probing: the op is capped by the
// device's practical pure-write-stream bandwidth (~5.4 TB/s sustained,
// measured invariant across STG.128/STG.256/.cs/bulk-TMA/batched paths and
// with x pinned in L2). Best-measured structure:
//   - per-thread (i, h) is loop-invariant (grid stride multiple of 256 f8),
//     so each thread's 8 W + 8 b floats live in registers,
//   - hot loop = 1 LDG + 8 FFMA + 1 st.global.cs.v8.f32,
//   - each warp store wavefront is 1KB fully dense (8 x 128B lines),
//   - balanced persistent grid: 148 SMs x 8 blocks x 256 threads.

#define C_IN   128
#define C_OUT  16
#define TOTAL_F8 8388608u               // 2^23 float8 units (256 MB / 32B)

#define NBLOCKS  (148 * 8)
#define NTHREADS 256
#define STRIDE   ((unsigned)NBLOCKS * NTHREADS)   // 303,104 (multiple of 256)

__global__ __launch_bounds__(NTHREADS, 8)
void real_embedding_kernel(const float* __restrict__ x,
                           const float* __restrict__ W,
                           const float* __restrict__ b,
                           float* __restrict__ out)
{
    const unsigned tid0 = blockIdx.x * NTHREADS + threadIdx.x;

    // STRIDE is a multiple of 256 -> per-thread (i, h) invariant across loop.
    const unsigned h = tid0 & 1u;            // which 8-float half of the 16
    const unsigned i = (tid0 >> 1) & 127u;   // input feature

    // Hoist this thread's W/b slice into registers (one-time, coalesced).
    const float4* W4 = (const float4*)(W + i * C_OUT + h * 8);
    const float4* B4 = (const float4*)(b + i * C_OUT + h * 8);
    const float4 w0 = W4[0], w1 = W4[1];
    const float4 c0 = B4[0], c1 = B4[1];

    const unsigned bt_step = STRIDE >> 8;
    unsigned bt = tid0 >> 8;

#pragma unroll 1
    for (unsigned gid = tid0; gid < TOTAL_F8; gid += STRIDE, bt += bt_step) {
        const float xv = __ldg(x + (size_t)bt * C_IN + i);

        const float r0 = fmaf(xv, w0.x, c0.x), r1 = fmaf(xv, w0.y, c0.y);
        const float r2 = fmaf(xv, w0.z, c0.z), r3 = fmaf(xv, w0.w, c0.w);
        const float r4 = fmaf(xv, w1.x, c1.x), r5 = fmaf(xv, w1.y, c1.y);
        const float r6 = fmaf(xv, w1.z, c1.z), r7 = fmaf(xv, w1.w, c1.w);

        float* dst = out + (size_t)gid * 8;   // 32B-aligned; warp-dense 1KB
        // Streaming (evict-first) 256-bit store: output lines are dead after
        // write, don't let them displace anything useful in L2.
        asm volatile("st.global.cs.v8.f32 [%0], {%1,%2,%3,%4,%5,%6,%7,%8};" ::
            "l"(dst), "f"(r0),"f"(r1),"f"(r2),"f"(r3),
                      "f"(r4),"f"(r5),"f"(r6),"f"(r7) : "memory");
    }
}

extern "C" void kernel_launch(void* const* d_in, const int* in_sizes, int n_in,
                              void* d_out, int out_size) {
    const float* x = (const float*)d_in[0];
    const float* W = (const float*)d_in[1];
    const float* b = (const float*)d_in[2];
    float* out = (float*)d_out;

    (void)in_sizes; (void)n_in; (void)out_size;

    real_embedding_kernel<<<NBLOCKS, NTHREADS>>>(x, W, b, out);
}